// round 17
// baseline (speedup 1.0000x reference)
#include <cuda_runtime.h>
#include <cuda_fp16.h>
#include <mma.h>

using namespace nvcuda;

#define NN 50000
#define NE 800000
#define NG 128
#define NH 4
#define HD 64
#define HC 256      // NH*HD
#define JK 576      // 64 + 256 + 256

// ---------------- scratch (static device globals; no allocation) ----------
__device__ __half g_hh  [NN*HC];   // GEMM output, fp16 (GAT gather input)
__device__ __half g_preh[NN*HC];   // relu(gat)+bias fp16 (LP base)
__device__ unsigned char g_prehq[NN*HC];  // quantized preh*dis (LP1 gather input)
__device__ unsigned char g_acchq[NN*HC];  // quantized LP1out*dis, fixed 1/255 (LP2 input)
__device__ float  g_qscale[NN];    // per-node scale for prehq
__device__ __half g_h1h [NN*HC];   // h1 fp16 (pool + GEMM2 A)
__device__ __half g_h2h [NN*HC];   // h2 fp16 (pool)
__device__ __half g_w1hi[64*256];
__device__ __half g_w1lo[64*256];
__device__ __half g_w2hi[256*256];
__device__ __half g_w2lo[256*256];
__device__ float  g_es  [NN*NH];
__device__ float  g_ed  [NN*NH];
__device__ float  g_alpha[NE*NH];  // raw exp(e), CSR order
__device__ float  g_dis [NN];
__device__ int    g_cnt [NN];
__device__ int    g_pos [NN];
__device__ int    g_rowptr[NN+1];
__device__ int    g_srcs[NE];

// ---------------- helpers --------------------------------------------------
__device__ __forceinline__ uint2 pack_half4(float4 v) {
    __half2 lo = __floats2half2_rn(v.x, v.y);
    __half2 hi = __floats2half2_rn(v.z, v.w);
    uint2 r;
    r.x = *(unsigned*)&lo;
    r.y = *(unsigned*)&hi;
    return r;
}

__device__ __forceinline__ void fma8(float* acc, float a, uint4 r) {
    __half2* hp = (__half2*)&r;
    #pragma unroll
    for (int q = 0; q < 4; q++) {
        float2 f = __half22float2(hp[q]);
        acc[2*q]   += a * f.x;
        acc[2*q+1] += a * f.y;
    }
}

__device__ __forceinline__ void unpack8(float* o, uint4 r) {
    __half2* hp = (__half2*)&r;
    #pragma unroll
    for (int q = 0; q < 4; q++) {
        float2 f = __half22float2(hp[q]);
        o[2*q] = f.x; o[2*q+1] = f.y;
    }
}

__device__ __forceinline__ uint4 pack_half8(const float* v) {
    uint4 r;
    __half2 h0 = __floats2half2_rn(v[0], v[1]);
    __half2 h1 = __floats2half2_rn(v[2], v[3]);
    __half2 h2 = __floats2half2_rn(v[4], v[5]);
    __half2 h3 = __floats2half2_rn(v[6], v[7]);
    r.x = *(unsigned*)&h0; r.y = *(unsigned*)&h1;
    r.z = *(unsigned*)&h2; r.w = *(unsigned*)&h3;
    return r;
}

// 8 floats (>=0) -> 8 uchar packed in uint2, scaled by inv
__device__ __forceinline__ uint2 pack_u8x8(const float* v, float inv) {
    unsigned q[8];
    #pragma unroll
    for (int k = 0; k < 8; k++) {
        int qi = (int)rintf(v[k] * inv);
        q[k] = (unsigned)(qi < 0 ? 0 : (qi > 255 ? 255 : qi));
    }
    uint2 r;
    r.x = q[0] | (q[1] << 8) | (q[2] << 16) | (q[3] << 24);
    r.y = q[4] | (q[5] << 8) | (q[6] << 16) | (q[7] << 24);
    return r;
}

// acc[k] += s * byte_k(r)
__device__ __forceinline__ void fma8_u8(float* acc, float s, uint2 r) {
    #pragma unroll
    for (int k = 0; k < 4; k++)
        acc[k] += s * (float)((r.x >> (8 * k)) & 255u);
    #pragma unroll
    for (int k = 0; k < 4; k++)
        acc[4 + k] += s * (float)((r.y >> (8 * k)) & 255u);
}

// Both weight splits in one launch.
__global__ void __launch_bounds__(256)
wsplit_kernel(const float* __restrict__ W1, const float* __restrict__ W2,
              __half* __restrict__ w1hi, __half* __restrict__ w1lo,
              __half* __restrict__ w2hi, __half* __restrict__ w2lo) {
    const int n1 = 64 * 256, n2 = 256 * 256;
    int t = blockIdx.x * blockDim.x + threadIdx.x;
    if (t < n1) {
        float v = W1[t];
        __half h = __float2half_rn(v);
        w1hi[t] = h;
        w1lo[t] = __float2half_rn(v - __half2float(h));
    } else if (t < n1 + n2) {
        int i = t - n1;
        float v = W2[i];
        __half h = __float2half_rn(v);
        w2hi[i] = h;
        w2lo[i] = __float2half_rn(v - __half2float(h));
    }
}

// ---------------- CSR construction ----------------------------------------
__global__ void __launch_bounds__(256)
deg_kernel(const int* __restrict__ dst, int* __restrict__ cnt) {
    int e = blockIdx.x * blockDim.x + threadIdx.x;
    if (e >= NE) return;
    atomicAdd(&cnt[dst[e]], 1);
}

__global__ void csr_scan_kernel(const int* __restrict__ cnt, int* __restrict__ rowptr,
                                int* __restrict__ pos, float* __restrict__ dis) {
    __shared__ int part[1024];
    int tid = threadIdx.x;
    const int CH = (NN + 1023) / 1024;
    int start = tid * CH;
    int end = start + CH < NN ? start + CH : NN;
    int s = 0;
    for (int i = start; i < end; i++) s += cnt[i];
    part[tid] = s;
    __syncthreads();
    for (int off = 1; off < 1024; off <<= 1) {
        int u = (tid >= off) ? part[tid - off] : 0;
        __syncthreads();
        part[tid] += u;
        __syncthreads();
    }
    int base = (tid > 0) ? part[tid - 1] : 0;
    for (int i = start; i < end; i++) {
        rowptr[i] = base;
        pos[i] = base;
        int c = cnt[i];
        dis[i] = (c > 0) ? rsqrtf((float)c) : 0.0f;
        base += c;
    }
    if (tid == 1023) rowptr[NN] = part[1023];
}

__global__ void __launch_bounds__(256)
csr_perm_kernel(const int* __restrict__ src, const int* __restrict__ dst,
                int* __restrict__ pos, int* __restrict__ srcs) {
    int e = blockIdx.x * blockDim.x + threadIdx.x;
    if (e >= NE) return;
    int p = atomicAdd(&pos[dst[e]], 1);
    srcs[p] = src[e];
}

// ---------------- WMMA GEMM (fp32 A, split 3-product) + attn scores --------
template <int K>
__global__ void __launch_bounds__(256)
gemm_wmma_f32_kernel(const float* __restrict__ A,
                     const __half* __restrict__ Whi, const __half* __restrict__ Wlo,
                     __half* __restrict__ Ch,
                     float* __restrict__ es, float* __restrict__ ed,
                     const float* __restrict__ a_s, const float* __restrict__ a_d,
                     int nrows) {
    __shared__ __half sAhi[128 * 24];
    __shared__ __half sAlo[128 * 24];
    __shared__ float  sC[128 * 68];
    __shared__ float  sa[64], sdv[64];

    const int hd = blockIdx.x;
    const int col0 = hd * 64;
    const int row0 = blockIdx.y * 128;
    const int warp = threadIdx.x >> 5;
    const int wm = warp >> 1;
    const int wn = warp & 1;

    if (threadIdx.x < 64)       sa[threadIdx.x] = a_s[hd * 64 + threadIdx.x];
    else if (threadIdx.x < 128) sdv[threadIdx.x - 64] = a_d[hd * 64 + threadIdx.x - 64];

    wmma::fragment<wmma::accumulator, 16, 16, 16, float> acc[2][2];
    #pragma unroll
    for (int i = 0; i < 2; i++)
        #pragma unroll
        for (int j = 0; j < 2; j++) wmma::fill_fragment(acc[i][j], 0.0f);

    for (int k0 = 0; k0 < K; k0 += 16) {
        {
            int r = threadIdx.x >> 1;
            int seg = threadIdx.x & 1;
            int gr = row0 + r;
            float v[8];
            if (gr < nrows) {
                float4 f0 = *(const float4*)&A[(long)gr * K + k0 + seg * 8];
                float4 f1 = *(const float4*)&A[(long)gr * K + k0 + seg * 8 + 4];
                v[0]=f0.x; v[1]=f0.y; v[2]=f0.z; v[3]=f0.w;
                v[4]=f1.x; v[5]=f1.y; v[6]=f1.z; v[7]=f1.w;
            } else {
                #pragma unroll
                for (int q = 0; q < 8; q++) v[q] = 0.f;
            }
            float h[8], l[8];
            #pragma unroll
            for (int q = 0; q < 8; q++) {
                __half hh = __float2half_rn(v[q]);
                h[q] = __half2float(hh);
                l[q] = v[q] - h[q];
            }
            *(uint4*)&sAhi[r * 24 + seg * 8] = pack_half8(h);
            *(uint4*)&sAlo[r * 24 + seg * 8] = pack_half8(l);
        }
        __syncthreads();

        wmma::fragment<wmma::matrix_a, 16, 16, 16, __half, wmma::row_major> ahi[2], alo[2];
        wmma::fragment<wmma::matrix_b, 16, 16, 16, __half, wmma::row_major> bhi[2], blo[2];
        #pragma unroll
        for (int i = 0; i < 2; i++) {
            wmma::load_matrix_sync(ahi[i], &sAhi[(wm * 32 + i * 16) * 24], 24);
            wmma::load_matrix_sync(alo[i], &sAlo[(wm * 32 + i * 16) * 24], 24);
        }
        #pragma unroll
        for (int j = 0; j < 2; j++) {
            int col = col0 + wn * 32 + j * 16;
            wmma::load_matrix_sync(bhi[j], &Whi[(long)k0 * 256 + col], 256);
            wmma::load_matrix_sync(blo[j], &Wlo[(long)k0 * 256 + col], 256);
        }
        #pragma unroll
        for (int i = 0; i < 2; i++)
            #pragma unroll
            for (int j = 0; j < 2; j++) {
                wmma::mma_sync(acc[i][j], ahi[i], bhi[j], acc[i][j]);
                wmma::mma_sync(acc[i][j], ahi[i], blo[j], acc[i][j]);
                wmma::mma_sync(acc[i][j], alo[i], bhi[j], acc[i][j]);
            }
        __syncthreads();
    }

    #pragma unroll
    for (int i = 0; i < 2; i++)
        #pragma unroll
        for (int j = 0; j < 2; j++)
            wmma::store_matrix_sync(&sC[(wm * 32 + i * 16) * 68 + wn * 32 + j * 16],
                                    acc[i][j], 68, wmma::mem_row_major);
    __syncthreads();

    for (int idx = threadIdx.x; idx < 128 * 16; idx += 256) {
        int r = idx >> 4, c4 = idx & 15;
        int gr = row0 + r;
        if (gr < nrows) {
            float4 v = *(float4*)&sC[r * 68 + c4 * 4];
            *(uint2*)&Ch[(long)gr * 256 + col0 + c4 * 4] = pack_half4(v);
        }
    }
    if (threadIdx.x < 128) {
        int r = threadIdx.x;
        int gr = row0 + r;
        if (gr < nrows) {
            float s = 0.f, d = 0.f;
            #pragma unroll 8
            for (int c = 0; c < 64; c++) {
                float v = sC[r * 68 + c];
                s += v * sa[c];
                d += v * sdv[c];
            }
            es[gr * NH + hd] = s;
            ed[gr * NH + hd] = d;
        }
    }
}

// ---------------- WMMA GEMM (fp16 A, 2-product) + attn scores --------------
template <int K>
__global__ void __launch_bounds__(256)
gemm_wmma_f16_kernel(const __half* __restrict__ A,
                     const __half* __restrict__ Whi, const __half* __restrict__ Wlo,
                     __half* __restrict__ Ch,
                     float* __restrict__ es, float* __restrict__ ed,
                     const float* __restrict__ a_s, const float* __restrict__ a_d,
                     int nrows) {
    __shared__ __half sA[128 * 24];
    __shared__ float  sC[128 * 68];
    __shared__ float  sa[64], sdv[64];

    const int hd = blockIdx.x;
    const int col0 = hd * 64;
    const int row0 = blockIdx.y * 128;
    const int warp = threadIdx.x >> 5;
    const int wm = warp >> 1;
    const int wn = warp & 1;

    if (threadIdx.x < 64)       sa[threadIdx.x] = a_s[hd * 64 + threadIdx.x];
    else if (threadIdx.x < 128) sdv[threadIdx.x - 64] = a_d[hd * 64 + threadIdx.x - 64];

    wmma::fragment<wmma::accumulator, 16, 16, 16, float> acc[2][2];
    #pragma unroll
    for (int i = 0; i < 2; i++)
        #pragma unroll
        for (int j = 0; j < 2; j++) wmma::fill_fragment(acc[i][j], 0.0f);

    for (int k0 = 0; k0 < K; k0 += 16) {
        {
            int r = threadIdx.x >> 1;
            int seg = threadIdx.x & 1;
            int gr = row0 + r;
            if (gr < nrows)
                *(uint4*)&sA[r * 24 + seg * 8] = *(const uint4*)&A[(long)gr * K + k0 + seg * 8];
            else
                *(uint4*)&sA[r * 24 + seg * 8] = make_uint4(0, 0, 0, 0);
        }
        __syncthreads();

        wmma::fragment<wmma::matrix_a, 16, 16, 16, __half, wmma::row_major> a[2];
        wmma::fragment<wmma::matrix_b, 16, 16, 16, __half, wmma::row_major> bhi[2], blo[2];
        #pragma unroll
        for (int i = 0; i < 2; i++)
            wmma::load_matrix_sync(a[i], &sA[(wm * 32 + i * 16) * 24], 24);
        #pragma unroll
        for (int j = 0; j < 2; j++) {
            int col = col0 + wn * 32 + j * 16;
            wmma::load_matrix_sync(bhi[j], &Whi[(long)k0 * 256 + col], 256);
            wmma::load_matrix_sync(blo[j], &Wlo[(long)k0 * 256 + col], 256);
        }
        #pragma unroll
        for (int i = 0; i < 2; i++)
            #pragma unroll
            for (int j = 0; j < 2; j++) {
                wmma::mma_sync(acc[i][j], a[i], bhi[j], acc[i][j]);
                wmma::mma_sync(acc[i][j], a[i], blo[j], acc[i][j]);
            }
        __syncthreads();
    }

    #pragma unroll
    for (int i = 0; i < 2; i++)
        #pragma unroll
        for (int j = 0; j < 2; j++)
            wmma::store_matrix_sync(&sC[(wm * 32 + i * 16) * 68 + wn * 32 + j * 16],
                                    acc[i][j], 68, wmma::mem_row_major);
    __syncthreads();

    for (int idx = threadIdx.x; idx < 128 * 16; idx += 256) {
        int r = idx >> 4, c4 = idx & 15;
        int gr = row0 + r;
        if (gr < nrows) {
            float4 v = *(float4*)&sC[r * 68 + c4 * 4];
            *(uint2*)&Ch[(long)gr * 256 + col0 + c4 * 4] = pack_half4(v);
        }
    }
    if (threadIdx.x < 128) {
        int r = threadIdx.x;
        int gr = row0 + r;
        if (gr < nrows) {
            float s = 0.f, d = 0.f;
            #pragma unroll 8
            for (int c = 0; c < 64; c++) {
                float v = sC[r * 68 + c];
                s += v * sa[c];
                d += v * sdv[c];
            }
            es[gr * NH + hd] = s;
            ed[gr * NH + hd] = d;
        }
    }
}

// ---------------- GAT gather with fused softmax (warp per node) -----------
__global__ void __launch_bounds__(256)
gat_gather_kernel(const int* __restrict__ rowptr, const int* __restrict__ srcs,
                  const __half* __restrict__ h,
                  const float* __restrict__ es, const float* __restrict__ ed,
                  float* __restrict__ alpha,
                  const float* __restrict__ bias,
                  const float* __restrict__ dis,
                  __half* __restrict__ outh,
                  unsigned char* __restrict__ outq,
                  float* __restrict__ qscale) {
    int t = blockIdx.x * blockDim.x + threadIdx.x;
    if (t >= NN * 32) return;
    int n = t >> 5, j = t & 31;
    int hd = j >> 3, g = j & 7;
    int b = rowptr[n], e_ = rowptr[n + 1];
    float edn = ed[n * NH + hd];

    float den = 0.f;
    for (int i = b + g; i < e_; i += 8) {
        float v = es[srcs[i] * NH + hd] + edn;
        v = (v >= 0.f) ? v : 0.2f * v;
        float ex = __expf(fminf(v, 80.f));
        alpha[i * NH + hd] = ex;
        den += ex;
    }
    #pragma unroll
    for (int off = 4; off > 0; off >>= 1)
        den += __shfl_down_sync(0xffffffffu, den, off, 8);
    den = __shfl_sync(0xffffffffu, den, 0, 8);
    float inv = (den > 0.f) ? 1.0f / den : 1.0f;
    __syncwarp();

    float acc[8] = {};
    for (int i = b; i < e_; i++) {
        int s = srcs[i];
        float a = alpha[i * NH + hd];
        uint4 r = *(const uint4*)&h[(long)s * HC + j * 8];
        fma8(acc, a, r);
    }
    float4 b0 = *(const float4*)&bias[j * 8];
    float4 b1 = *(const float4*)&bias[j * 8 + 4];
    acc[0] = fmaxf(acc[0] * inv + b0.x, 0.f); acc[1] = fmaxf(acc[1] * inv + b0.y, 0.f);
    acc[2] = fmaxf(acc[2] * inv + b0.z, 0.f); acc[3] = fmaxf(acc[3] * inv + b0.w, 0.f);
    acc[4] = fmaxf(acc[4] * inv + b1.x, 0.f); acc[5] = fmaxf(acc[5] * inv + b1.y, 0.f);
    acc[6] = fmaxf(acc[6] * inv + b1.z, 0.f); acc[7] = fmaxf(acc[7] * inv + b1.w, 0.f);
    long base_off = (long)n * HC + j * 8;
    *(uint4*)&outh[base_off] = pack_half8(acc);

    // quantize preh * dis[n] with per-node scale (warp max)
    float dn = dis[n];
    float sc[8];
    float m = 0.f;
    #pragma unroll
    for (int q = 0; q < 8; q++) { sc[q] = acc[q] * dn; m = fmaxf(m, sc[q]); }
    #pragma unroll
    for (int off = 16; off > 0; off >>= 1)
        m = fmaxf(m, __shfl_xor_sync(0xffffffffu, m, off));
    float qinv = (m > 0.f) ? 255.0f / m : 0.0f;
    if (j == 0) qscale[n] = (m > 0.f) ? m / 255.0f : 0.0f;
    *(uint2*)&outq[base_off] = pack_u8x8(sc, qinv);
}

// ---------------- LP gather 1: int8 rows with per-node scale ---------------
__global__ void __launch_bounds__(256)
lp_gather1_kernel(const int* __restrict__ rowptr, const int* __restrict__ srcs,
                  const unsigned char* __restrict__ qrows,
                  const float* __restrict__ qscale,
                  const float* __restrict__ dis,
                  const __half* __restrict__ base,
                  unsigned char* __restrict__ outq) {
    int t = blockIdx.x * blockDim.x + threadIdx.x;
    if (t >= NN * 32) return;
    int n = t >> 5, j = t & 31;
    int b = rowptr[n], e_ = rowptr[n + 1];
    float dn = dis[n];
    float acc[8] = {};
    for (int i = b; i < e_; i++) {
        int s = srcs[i];
        float qs = qscale[s];
        uint2 r = *(const uint2*)&qrows[(long)s * HC + j * 8];
        fma8_u8(acc, qs, r);
    }
    long base_off = (long)n * HC + j * 8;
    float bs[8];
    unpack8(bs, *(const uint4*)&base[base_off]);
    float o[8];
    #pragma unroll
    for (int q = 0; q < 8; q++) {
        float v = fminf(fmaxf(0.5f * dn * acc[q] + 0.5f * bs[q], 0.f), 1.f);
        o[q] = v * dn;   // in [0,1]
    }
    *(uint2*)&outq[base_off] = pack_u8x8(o, 255.0f);
}

// ---------------- LP gather 2: int8 rows, fixed 1/255 scale ----------------
__global__ void __launch_bounds__(256)
lp_gather2_kernel(const int* __restrict__ rowptr, const int* __restrict__ srcs,
                  const unsigned char* __restrict__ qrows,
                  const float* __restrict__ dis,
                  const __half* __restrict__ base,
                  __half* __restrict__ outf) {
    int t = blockIdx.x * blockDim.x + threadIdx.x;
    if (t >= NN * 32) return;
    int n = t >> 5, j = t & 31;
    int b = rowptr[n], e_ = rowptr[n + 1];
    float dn = dis[n];
    float acc[8] = {};
    for (int i = b; i < e_; i++) {
        int s = srcs[i];
        uint2 r = *(const uint2*)&qrows[(long)s * HC + j * 8];
        fma8_u8(acc, 1.0f, r);
    }
    long base_off = (long)n * HC + j * 8;
    float bs[8];
    unpack8(bs, *(const uint4*)&base[base_off]);
    const float k = 0.5f / 255.0f;
    float o[8];
    #pragma unroll
    for (int q = 0; q < 8; q++)
        o[q] = fminf(fmaxf(k * dn * acc[q] + 0.5f * bs[q], 0.f), 1.f);
    *(uint4*)&outf[base_off] = pack_half8(o);
}

// ---------------- Fused pooling + head MLPs (one block per graph) ----------
__device__ __forceinline__ int lower_bound_batch(const int* __restrict__ batch, int key) {
    int lo = 0, hi = NN;
    while (lo < hi) {
        int mid = (lo + hi) >> 1;
        if (batch[mid] < key) lo = mid + 1; else hi = mid;
    }
    return lo;
}

__global__ void __launch_bounds__(JK)
poolhead_kernel(const float* __restrict__ x,
                const __half* __restrict__ h1, const __half* __restrict__ h2,
                const int* __restrict__ batch,
                const float* __restrict__ clin,
                const float* __restrict__ pp_w1, const float* __restrict__ pp_b1,
                const float* __restrict__ pp_w2, const float* __restrict__ pp_b2,
                const float* __restrict__ cl_w1, const float* __restrict__ cl_b1,
                const float* __restrict__ cl_w2, const float* __restrict__ cl_b2,
                const float* __restrict__ h_w1, const float* __restrict__ h_b1,
                const float* __restrict__ h_w2, const float* __restrict__ h_b2,
                const float* __restrict__ h_w3, const float* __restrict__ h_b3,
                float* __restrict__ out) {
    __shared__ float g[JK];
    __shared__ float t1[256];
    __shared__ float z[160];
    __shared__ float c1s[64];
    __shared__ float t3[64];
    __shared__ float t4[32];
    __shared__ int s_start, s_end;
    int b = blockIdx.x, tid = threadIdx.x;

    if (tid == 0) {
        s_start = lower_bound_batch(batch, b);
        s_end   = lower_bound_batch(batch, b + 1);
    }
    __syncthreads();
    int start = s_start, end = s_end;
    {
        float s = 0.f;
        if (tid < 64) {
            for (int n = start; n < end; n++) s += x[(long)n * 64 + tid];
        } else if (tid < 320) {
            int c = tid - 64;
            for (int n = start; n < end; n++) s += __half2float(h1[(long)n * HC + c]);
        } else {
            int c = tid - 320;
            for (int n = start; n < end; n++) s += __half2float(h2[(long)n * HC + c]);
        }
        float cnt = fmaxf((float)(end - start), 1.0f);
        g[tid] = s / cnt;
    }
    __syncthreads();

    if (tid < 256) {
        float o = pp_b1[tid];
        for (int k = 0; k < JK; k++) o += g[k] * pp_w1[k * 256 + tid];
        t1[tid] = o > 0.f ? o : 0.f;
    } else if (tid < 320) {
        int c = tid - 256;
        float o = cl_b1[c];
        for (int k = 0; k < 32; k++) o += clin[b * 32 + k] * cl_w1[k * 64 + c];
        c1s[c] = o > 0.f ? o : 0.f;
    }
    __syncthreads();
    if (tid < 128) {
        float o = pp_b2[tid];
        for (int k = 0; k < 256; k++) o += t1[k] * pp_w2[k * 128 + tid];
        z[tid] = o;
    } else if (tid < 160) {
        int c = tid - 128;
        float o = cl_b2[c];
        for (int k = 0; k < 64; k++) o += c1s[k] * cl_w2[k * 32 + c];
        z[128 + c] = o;
    }
    __syncthreads();
    if (tid < 64) {
        float o = h_b1[tid];
        for (int k = 0; k < 160; k++) o += z[k] * h_w1[k * 64 + tid];
        t3[tid] = o > 0.f ? o : 0.f;
    }
    __syncthreads();
    if (tid < 32) {
        float o = h_b2[tid];
        for (int k = 0; k < 64; k++) o += t3[k] * h_w2[k * 32 + tid];
        t4[tid] = o > 0.f ? o : 0.f;
    }
    __syncthreads();
    if (tid < 2) {
        float o = h_b3[tid];
        for (int k = 0; k < 32; k++) o += t4[k] * h_w3[k * 2 + tid];
        out[b * 2 + tid] = o;
    }
}

// ---------------- launch --------------------------------------------------
static inline int cdiv(long a, int b) { return (int)((a + b - 1) / b); }

extern "C" void kernel_launch(void* const* d_in, const int* in_sizes, int n_in,
                              void* d_out, int out_size) {
    const float* x     = (const float*)d_in[0];
    const int*   ei    = (const int*)  d_in[1];
    const int*   batch = (const int*)  d_in[2];
    const float* clin  = (const float*)d_in[3];
    const float* W1  = (const float*)d_in[4];
    const float* a1s = (const float*)d_in[5];
    const float* a1d = (const float*)d_in[6];
    const float* b1  = (const float*)d_in[7];
    const float* W2  = (const float*)d_in[8];
    const float* a2s = (const float*)d_in[9];
    const float* a2d = (const float*)d_in[10];
    const float* b2  = (const float*)d_in[11];
    const float* pp_w1 = (const float*)d_in[12];
    const float* pp_b1 = (const float*)d_in[13];
    const float* pp_w2 = (const float*)d_in[14];
    const float* pp_b2 = (const float*)d_in[15];
    const float* cl_w1 = (const float*)d_in[16];
    const float* cl_b1 = (const float*)d_in[17];
    const float* cl_w2 = (const float*)d_in[18];
    const float* cl_b2 = (const float*)d_in[19];
    const float* h_w1 = (const float*)d_in[20];
    const float* h_b1 = (const float*)d_in[21];
    const float* h_w2 = (const float*)d_in[22];
    const float* h_b2 = (const float*)d_in[23];
    const float* h_w3 = (const float*)d_in[24];
    const float* h_b3 = (const float*)d_in[25];
    float* out = (float*)d_out;

    const int* src = ei;
    const int* dst = ei + NE;

    float *p_es, *p_ed, *p_alpha, *p_dis, *p_qscale;
    __half *p_hh, *p_preh, *p_h1h, *p_h2h;
    unsigned char *p_prehq, *p_acchq;
    __half *p_w1hi, *p_w1lo, *p_w2hi, *p_w2lo;
    int *p_cnt, *p_pos, *p_rowptr, *p_srcs;
    cudaGetSymbolAddress((void**)&p_hh,    g_hh);
    cudaGetSymbolAddress((void**)&p_preh,  g_preh);
    cudaGetSymbolAddress((void**)&p_prehq, g_prehq);
    cudaGetSymbolAddress((void**)&p_acchq, g_acchq);
    cudaGetSymbolAddress((void**)&p_qscale,g_qscale);
    cudaGetSymbolAddress((void**)&p_h1h,   g_h1h);
    cudaGetSymbolAddress((void**)&p_h2h,   g_h2h);
    cudaGetSymbolAddress((void**)&p_w1hi,  g_w1hi);
    cudaGetSymbolAddress((void**)&p_w1lo,  g_w1lo);
    cudaGetSymbolAddress((void**)&p_w2hi,  g_w2hi);
    cudaGetSymbolAddress((void**)&p_w2lo,  g_w2lo);
    cudaGetSymbolAddress((void**)&p_es,    g_es);
    cudaGetSymbolAddress((void**)&p_ed,    g_ed);
    cudaGetSymbolAddress((void**)&p_alpha, g_alpha);
    cudaGetSymbolAddress((void**)&p_dis,   g_dis);
    cudaGetSymbolAddress((void**)&p_cnt,   g_cnt);
    cudaGetSymbolAddress((void**)&p_pos,   g_pos);
    cudaGetSymbolAddress((void**)&p_rowptr,g_rowptr);
    cudaGetSymbolAddress((void**)&p_srcs,  g_srcs);

    const int TB = 256;

    // ---- CSR by dst ----
    cudaMemsetAsync(p_cnt, 0, NN * sizeof(int));
    deg_kernel<<<cdiv(NE, TB), TB>>>(dst, p_cnt);
    csr_scan_kernel<<<1, 1024>>>(p_cnt, p_rowptr, p_pos, p_dis);
    csr_perm_kernel<<<cdiv(NE, TB), TB>>>(src, dst, p_pos, p_srcs);

    // ---- weight splits (one launch) ----
    wsplit_kernel<<<cdiv(64 * 256 + 256 * 256, TB), TB>>>(
        W1, W2, p_w1hi, p_w1lo, p_w2hi, p_w2lo);

    dim3 ggrid(4, cdiv(NN, 128));

    for (int layer = 0; layer < 2; layer++) {
        const float* a_s = layer ? a2s : a1s;
        const float* a_d = layer ? a2d : a1d;
        const float* bb  = layer ? b2  : b1;

        if (layer == 0)
            gemm_wmma_f32_kernel<64><<<ggrid, TB>>>(x, p_w1hi, p_w1lo,
                                                    p_hh, p_es, p_ed, a_s, a_d, NN);
        else
            gemm_wmma_f16_kernel<256><<<ggrid, TB>>>(p_h1h, p_w2hi, p_w2lo,
                                                     p_hh, p_es, p_ed, a_s, a_d, NN);

        gat_gather_kernel<<<cdiv((long)NN * 32, TB), TB>>>(
            p_rowptr, p_srcs, p_hh, p_es, p_ed, p_alpha, bb, p_dis,
            p_preh, p_prehq, p_qscale);

        // LP iter 1: int8 gather (per-node scale) -> acchq (fixed scale)
        lp_gather1_kernel<<<cdiv((long)NN * 32, TB), TB>>>(
            p_rowptr, p_srcs, p_prehq, p_qscale, p_dis, p_preh, p_acchq);
        // LP iter 2: int8 gather (fixed scale) -> hXh fp16
        lp_gather2_kernel<<<cdiv((long)NN * 32, TB), TB>>>(
            p_rowptr, p_srcs, p_acchq, p_dis, p_preh,
            layer ? p_h2h : p_h1h);
    }

    // ================= fused pooling + heads =================
    poolhead_kernel<<<NG, JK>>>(x, p_h1h, p_h2h, batch, clin,
                                pp_w1, pp_b1, pp_w2, pp_b2,
                                cl_w1, cl_b1, cl_w2, cl_b2,
                                h_w1, h_b1, h_w2, h_b2, h_w3, h_b3,
                                out);
}